// round 6
// baseline (speedup 1.0000x reference)
#include <cuda_runtime.h>
#include <cstdint>

// Problem constants
#define M_ROWS (16 * 8192)   // B*N = 131072
#define DDIM 128
#define CDIM 64
#define INV_TEMP (1.0f / 6.0f)   // temp = 2*(1+192/96) = 6

// Pass-1 tiling
#define BR 128               // rows per block
#define NBLK (M_ROWS / BR)   // 1024
#define XS_STRIDE 132        // x tile row stride (floats)
#define DT_STRIDE 68         // dictT row stride (floats)
#define SC_STRIDE 68         // scores row stride

#define SMEM_FLOATS (128 * DT_STRIDE + BR * XS_STRIDE + BR * SC_STRIDE)
#define SMEM_BYTES (SMEM_FLOATS * 4)

#define P2_GRID (M_ROWS / 64)  // 2048

// -------------------- scratch (device globals; no allocs) --------------------
__device__ __align__(16) float g_q[(size_t)M_ROWS * CDIM];  // soft assignments
__device__ __align__(16) float g_t[(size_t)M_ROWS * CDIM];  // (s-m)/T
__device__ float g_logS[M_ROWS];
__device__ __align__(16) float g_fpart[CDIM * NBLK];        // partial col sums
__device__ float g_f[CDIM];
__device__ float g_klpart[P2_GRID];
__device__ float g_orthopart[16];

// -------------------- packed f32x2 helpers --------------------
__device__ __forceinline__ unsigned long long pack_dup(float x) {
    unsigned long long r;
    unsigned int xu = __float_as_uint(x);
    asm("mov.b64 %0, {%1, %1};" : "=l"(r) : "r"(xu));
    return r;
}
__device__ __forceinline__ void fma2(unsigned long long& acc,
                                     unsigned long long a,
                                     unsigned long long b) {
    asm("fma.rn.f32x2 %0, %1, %2, %0;" : "+l"(acc) : "l"(a), "l"(b));
}
__device__ __forceinline__ void unpack2(unsigned long long v, float& lo, float& hi) {
    unsigned int l, h;
    asm("mov.b64 {%0, %1}, %2;" : "=r"(l), "=r"(h) : "l"(v));
    lo = __uint_as_float(l);
    hi = __uint_as_float(h);
}

// -------------------- kernel 1: GEMM + softmax + topk + outputs --------------------
// 512 threads: 4 warps/SMSP for latency hiding; BR=128 tile, 1 CTA/SM.
__global__ __launch_bounds__(512, 1) void pass1_kernel(
    const float* __restrict__ x,
    const float* __restrict__ dict,
    float* __restrict__ out_common,
    float* __restrict__ out_res) {
    extern __shared__ float sm[];
    float* dictT = sm;                           // [128][DT_STRIDE]: dictT[d][c]
    float* x_s = sm + 128 * DT_STRIDE;           // [BR][XS_STRIDE]
    float* sc = x_s + BR * XS_STRIDE;            // [BR][SC_STRIDE] scores -> q

    const int tid = threadIdx.x;
    const int row0 = blockIdx.x * BR;

    // --- load dict transposed (conflict-free writes): 2048 float4
    {
        const int c = tid & 63;
        const int base = tid >> 6;  // 0..7
        const float4* dsrc = reinterpret_cast<const float4*>(dict);
#pragma unroll
        for (int j = 0; j < 4; ++j) {
            int dch = base + 8 * j;           // 0..31
            float4 v = dsrc[c * 32 + dch];
            int d0 = dch * 4;
            dictT[(d0 + 0) * DT_STRIDE + c] = v.x;
            dictT[(d0 + 1) * DT_STRIDE + c] = v.y;
            dictT[(d0 + 2) * DT_STRIDE + c] = v.z;
            dictT[(d0 + 3) * DT_STRIDE + c] = v.w;
        }
    }
    // --- load x tile (coalesced float4): 4096
    {
        const float4* xsrc = reinterpret_cast<const float4*>(x + (size_t)row0 * DDIM);
#pragma unroll
        for (int j = 0; j < 8; ++j) {
            int idx4 = tid + 512 * j;  // 0..4095
            float4 v = xsrc[idx4];
            int r = idx4 >> 5;
            int d0 = (idx4 & 31) * 4;
            *reinterpret_cast<float4*>(&x_s[r * XS_STRIDE + d0]) = v;
        }
    }
    __syncthreads();

    // --- GEMM: per thread 2 rows x 8 cols (f32x2 packed)
    {
        const int rg = tid >> 3;   // 0..63
        const int cg = tid & 7;    // 0..7
        const int r0 = rg * 2;
        unsigned long long acc[2][4];
#pragma unroll
        for (int i = 0; i < 2; ++i)
#pragma unroll
            for (int p = 0; p < 4; ++p) acc[i][p] = 0ull;

        const ulonglong2* dptr =
            reinterpret_cast<const ulonglong2*>(dictT) + cg * 2;  // 17 per d-row
#pragma unroll 8
        for (int k = 0; k < DDIM; ++k) {
            unsigned long long xp0 = pack_dup(x_s[(r0 + 0) * XS_STRIDE + k]);
            unsigned long long xp1 = pack_dup(x_s[(r0 + 1) * XS_STRIDE + k]);
            ulonglong2 dA = dptr[k * 17];
            ulonglong2 dB = dptr[k * 17 + 1];
            fma2(acc[0][0], xp0, dA.x); fma2(acc[0][1], xp0, dA.y);
            fma2(acc[0][2], xp0, dB.x); fma2(acc[0][3], xp0, dB.y);
            fma2(acc[1][0], xp1, dA.x); fma2(acc[1][1], xp1, dA.y);
            fma2(acc[1][2], xp1, dB.x); fma2(acc[1][3], xp1, dB.y);
        }
#pragma unroll
        for (int i = 0; i < 2; ++i) {
            float* dst = &sc[(r0 + i) * SC_STRIDE + cg * 8];
            float4 v0, v1;
            unpack2(acc[i][0], v0.x, v0.y);
            unpack2(acc[i][1], v0.z, v0.w);
            unpack2(acc[i][2], v1.x, v1.y);
            unpack2(acc[i][3], v1.z, v1.w);
            *reinterpret_cast<float4*>(dst) = v0;
            *reinterpret_cast<float4*>(dst + 4) = v1;
        }
    }
    __syncthreads();

    // --- row phase: 4 threads per row, 16 cols each
    {
        const int r = tid >> 2;    // 0..127
        const int qd = tid & 3;    // 0..3
        const int rowg = row0 + r;
        float* srow = &sc[r * SC_STRIDE + qd * 16];

        float s[16];
#pragma unroll
        for (int j = 0; j < 4; ++j) {
            float4 v = *reinterpret_cast<float4*>(srow + 4 * j);
            s[4 * j + 0] = v.x; s[4 * j + 1] = v.y;
            s[4 * j + 2] = v.z; s[4 * j + 3] = v.w;
        }

        // row max across 64 cols
        float m = s[0];
#pragma unroll
        for (int j = 1; j < 16; ++j) m = fmaxf(m, s[j]);
        m = fmaxf(m, __shfl_xor_sync(0xFFFFFFFFu, m, 1));
        m = fmaxf(m, __shfl_xor_sync(0xFFFFFFFFu, m, 2));

        // branchless local top-4 of 16 (strict > keeps lowest index on ties)
        float tv[4]; int ti[4];
        unsigned excl = 0;
#pragma unroll
        for (int p = 0; p < 4; ++p) {
            float bm = -1e30f; int bi = 0;
#pragma unroll
            for (int j = 0; j < 16; ++j) {
                bool ok = (((excl >> j) & 1u) == 0u) && (s[j] > bm);
                bm = ok ? s[j] : bm;
                bi = ok ? j : bi;
            }
            tv[p] = bm; ti[p] = qd * 16 + bi;
            excl |= 1u << bi;
        }

        // t = (s-m)/T -> global; e = exp(t); S
        float* tg = &g_t[(size_t)rowg * CDIM + qd * 16];
        float S = 0.0f;
#pragma unroll
        for (int j4 = 0; j4 < 4; ++j4) {
            float4 tvv4;
            float t0 = (s[4 * j4 + 0] - m) * INV_TEMP;
            float t1 = (s[4 * j4 + 1] - m) * INV_TEMP;
            float t2 = (s[4 * j4 + 2] - m) * INV_TEMP;
            float t3 = (s[4 * j4 + 3] - m) * INV_TEMP;
            tvv4.x = t0; tvv4.y = t1; tvv4.z = t2; tvv4.w = t3;
            *reinterpret_cast<float4*>(tg + 4 * j4) = tvv4;
            float e0 = __expf(t0), e1 = __expf(t1), e2 = __expf(t2), e3 = __expf(t3);
            s[4 * j4 + 0] = e0; s[4 * j4 + 1] = e1;
            s[4 * j4 + 2] = e2; s[4 * j4 + 3] = e3;
            S += e0 + e1 + e2 + e3;
        }
        S += __shfl_xor_sync(0xFFFFFFFFu, S, 1);
        S += __shfl_xor_sync(0xFFFFFFFFu, S, 2);
        float invS = 1.0f / S;
        if (qd == 0) g_logS[rowg] = __logf(S);

        // q -> global + smem (for column sums)
        float* qg = &g_q[(size_t)rowg * CDIM + qd * 16];
#pragma unroll
        for (int j4 = 0; j4 < 4; ++j4) {
            float4 v;
            v.x = s[4 * j4 + 0] * invS; v.y = s[4 * j4 + 1] * invS;
            v.z = s[4 * j4 + 2] * invS; v.w = s[4 * j4 + 3] * invS;
            *reinterpret_cast<float4*>(qg + 4 * j4) = v;
            *reinterpret_cast<float4*>(srow + 4 * j4) = v;
        }

        // two-stage merge of sorted top-4 lists (lower column range wins ties)
#pragma unroll
        for (int stage = 0; stage < 2; ++stage) {
            const int msk = 1 << stage;
            float pv[4]; int pi[4];
#pragma unroll
            for (int k2 = 0; k2 < 4; ++k2) {
                pv[k2] = __shfl_xor_sync(0xFFFFFFFFu, tv[k2], msk);
                pi[k2] = __shfl_xor_sync(0xFFFFFFFFu, ti[k2], msk);
            }
            bool iamA = ((qd & msk) == 0);
            float Av[4], Bv[4]; int Ai[4], Bi[4];
#pragma unroll
            for (int k2 = 0; k2 < 4; ++k2) {
                Av[k2] = iamA ? tv[k2] : pv[k2];
                Ai[k2] = iamA ? ti[k2] : pi[k2];
                Bv[k2] = iamA ? pv[k2] : tv[k2];
                Bi[k2] = iamA ? pi[k2] : ti[k2];
            }
            int a = 0, b = 0;
            float mv2[4]; int mi2[4];
#pragma unroll
            for (int k2 = 0; k2 < 4; ++k2) {
                bool ta = (Av[a] >= Bv[b]);
                mv2[k2] = ta ? Av[a] : Bv[b];
                mi2[k2] = ta ? Ai[a] : Bi[b];
                a += ta ? 1 : 0;
                b += ta ? 0 : 1;
            }
#pragma unroll
            for (int k2 = 0; k2 < 4; ++k2) { tv[k2] = mv2[k2]; ti[k2] = mi2[k2]; }
        }

        // softmax over top-4 (tv[0] is max)
        float e1 = __expf((tv[1] - tv[0]) * INV_TEMP);
        float e2 = __expf((tv[2] - tv[0]) * INV_TEMP);
        float e3 = __expf((tv[3] - tv[0]) * INV_TEMP);
        float wn = 1.0f / (1.0f + e1 + e2 + e3);
        float w0 = wn, w1 = e1 * wn, w2 = e2 * wn, w3 = e3 * wn;
        int i0 = ti[0], i1 = ti[1], i2 = ti[2], i3 = ti[3];

        // x_common / x_residual: this thread's 32 dims
        const float* xr = &x_s[r * XS_STRIDE];
        float* oc = out_common + (size_t)rowg * DDIM;
        float* orr = out_res + (size_t)rowg * DDIM;
        const int dbase = qd * 32;
#pragma unroll
        for (int dd = 0; dd < 32; dd += 4) {
            int d0 = dbase + dd;
            float4 xv = *reinterpret_cast<const float4*>(xr + d0);
            float4 cm;
            cm.x = w0 * dictT[(d0 + 0) * DT_STRIDE + i0] + w1 * dictT[(d0 + 0) * DT_STRIDE + i1] +
                   w2 * dictT[(d0 + 0) * DT_STRIDE + i2] + w3 * dictT[(d0 + 0) * DT_STRIDE + i3];
            cm.y = w0 * dictT[(d0 + 1) * DT_STRIDE + i0] + w1 * dictT[(d0 + 1) * DT_STRIDE + i1] +
                   w2 * dictT[(d0 + 1) * DT_STRIDE + i2] + w3 * dictT[(d0 + 1) * DT_STRIDE + i3];
            cm.z = w0 * dictT[(d0 + 2) * DT_STRIDE + i0] + w1 * dictT[(d0 + 2) * DT_STRIDE + i1] +
                   w2 * dictT[(d0 + 2) * DT_STRIDE + i2] + w3 * dictT[(d0 + 2) * DT_STRIDE + i3];
            cm.w = w0 * dictT[(d0 + 3) * DT_STRIDE + i0] + w1 * dictT[(d0 + 3) * DT_STRIDE + i1] +
                   w2 * dictT[(d0 + 3) * DT_STRIDE + i2] + w3 * dictT[(d0 + 3) * DT_STRIDE + i3];
            *reinterpret_cast<float4*>(oc + d0) = cm;
            float4 rs;
            rs.x = xv.x - cm.x; rs.y = xv.y - cm.y;
            rs.z = xv.z - cm.z; rs.w = xv.w - cm.w;
            *reinterpret_cast<float4*>(orr + d0) = rs;
        }
    }
    __syncthreads();

    // --- block column sums of q -> partials (no atomics, no zeroing)
    if (tid < CDIM) {
        float sum = 0.0f;
#pragma unroll 4
        for (int rr = 0; rr < BR; ++rr) sum += sc[rr * SC_STRIDE + tid];
        g_fpart[tid * NBLK + blockIdx.x] = sum;
    }
}

// -------------------- kernel 1b: reduce column-sum partials --------------------
__global__ __launch_bounds__(256) void reduce_f_kernel() {
    __shared__ float ws[8];
    const int c = blockIdx.x;
    const int tid = threadIdx.x;
    const float* src = &g_fpart[c * NBLK];
    float sum = 0.0f;
#pragma unroll
    for (int j = 0; j < NBLK / 256; ++j) sum += src[tid + 256 * j];
#pragma unroll
    for (int o = 16; o; o >>= 1) sum += __shfl_xor_sync(0xFFFFFFFFu, sum, o);
    if ((tid & 31) == 0) ws[tid >> 5] = sum;
    __syncthreads();
    if (tid == 0) {
        float t = 0.0f;
#pragma unroll
        for (int i = 0; i < 8; ++i) t += ws[i];
        g_f[c] = t;
    }
}

// -------------------- kernel 2: KL (no per-element transcendentals) --------------------
__global__ __launch_bounds__(256) void pass2_kernel() {
    __shared__ float invf_s[CDIM], lw_s[CDIM];  // 1/f, logf/f
    __shared__ float wsum[8];
    const int tid = threadIdx.x;
    if (tid < CDIM) {
        float f = g_f[tid];
        invf_s[tid] = 1.0f / f;
        lw_s[tid] = __logf(f) / f;
    }
    __syncthreads();

    const int r = blockIdx.x * 64 + (tid >> 2);
    const int qd = tid & 3;
    const int c0 = qd * 16;
    const float4* qp = reinterpret_cast<const float4*>(g_q + (size_t)r * CDIM + c0);
    const float4* tp = reinterpret_cast<const float4*>(g_t + (size_t)r * CDIM + c0);

    float W = 0.0f, V = 0.0f, L = 0.0f;
#pragma unroll
    for (int j4 = 0; j4 < 4; ++j4) {
        float4 qv = qp[j4];
        float4 tv = tp[j4];
        float qa[4] = {qv.x, qv.y, qv.z, qv.w};
        float ta[4] = {tv.x, tv.y, tv.z, tv.w};
#pragma unroll
        for (int i = 0; i < 4; ++i) {
            int c = c0 + j4 * 4 + i;
            float u = qa[i] * qa[i];
            float a = u * invf_s[c];
            W += a;
            V = fmaf(a, ta[i], V);
            L = fmaf(u, lw_s[c], L);
        }
    }
    W += __shfl_xor_sync(0xFFFFFFFFu, W, 1);
    W += __shfl_xor_sync(0xFFFFFFFFu, W, 2);
    V += __shfl_xor_sync(0xFFFFFFFFu, V, 1);
    V += __shfl_xor_sync(0xFFFFFFFFu, V, 2);
    L += __shfl_xor_sync(0xFFFFFFFFu, L, 1);
    L += __shfl_xor_sync(0xFFFFFFFFu, L, 2);

    float tm = 0.0f;
    if (qd == 0) tm = (V - L) / W - __logf(W) - g_logS[r];
    tm += __shfl_xor_sync(0xFFFFFFFFu, tm, 4);
    tm += __shfl_xor_sync(0xFFFFFFFFu, tm, 8);
    tm += __shfl_xor_sync(0xFFFFFFFFu, tm, 16);
    if ((tid & 31) == 0) wsum[tid >> 5] = tm;
    __syncthreads();
    if (tid == 0) {
        float t = 0.0f;
#pragma unroll
        for (int i = 0; i < 8; ++i) t += wsum[i];
        g_klpart[blockIdx.x] = t;
    }
}

// -------------------- kernel 3: ortho gram (split across 3 launches) ----------
#define OT_STRIDE 65
__global__ __launch_bounds__(256) void pass3_kernel(const float* __restrict__ dict,
                                                    int base) {
    __shared__ float dT[DDIM * OT_STRIDE];
    __shared__ float ws[8];
    const int tid = threadIdx.x;
    {
        const float4* dsrc = reinterpret_cast<const float4*>(dict);
#pragma unroll
        for (int it = 0; it < 8; ++it) {
            int idx = tid + 256 * it;
            int c = idx >> 5;
            int dch = idx & 31;
            float4 v = dsrc[c * 32 + dch];
            int d0 = dch * 4;
            dT[(d0 + 0) * OT_STRIDE + c] = v.x;
            dT[(d0 + 1) * OT_STRIDE + c] = v.y;
            dT[(d0 + 2) * OT_STRIDE + c] = v.z;
            dT[(d0 + 3) * OT_STRIDE + c] = v.w;
        }
    }
    __syncthreads();

    const int p = (base + blockIdx.x) * 256 + tid;
    const int i = p >> 6, j = p & 63;
    float dot = 0.0f;
#pragma unroll 8
    for (int d = 0; d < DDIM; ++d)
        dot = fmaf(dT[d * OT_STRIDE + i], dT[d * OT_STRIDE + j], dot);
    float diff = dot - ((i == j) ? 1.0f : 0.0f);
    float acc = diff * diff;

#pragma unroll
    for (int o = 16; o; o >>= 1) acc += __shfl_xor_sync(0xFFFFFFFFu, acc, o);
    if ((tid & 31) == 0) ws[tid >> 5] = acc;
    __syncthreads();
    if (tid == 0) {
        float t = 0.0f;
#pragma unroll
        for (int k = 0; k < 8; ++k) t += ws[k];
        g_orthopart[base + blockIdx.x] = t;
    }
}

// -------------------- kernel 4: finalize aux --------------------
__global__ __launch_bounds__(256) void pass4_kernel(float* __restrict__ out_aux) {
    __shared__ float ws[8];
    const int tid = threadIdx.x;
    float kl = 0.0f;
#pragma unroll
    for (int j = 0; j < P2_GRID / 256; ++j) kl += g_klpart[tid + 256 * j];
#pragma unroll
    for (int o = 16; o; o >>= 1) kl += __shfl_xor_sync(0xFFFFFFFFu, kl, o);
    if ((tid & 31) == 0) ws[tid >> 5] = kl;
    __syncthreads();
    if (tid == 0) {
        float t = 0.0f;
#pragma unroll
        for (int i = 0; i < 8; ++i) t += ws[i];
        float ortho = 0.0f;
#pragma unroll
        for (int i = 0; i < 16; ++i) ortho += g_orthopart[i];
        ortho /= (float)(CDIM * CDIM);
        float klm = t / (float)M_ROWS;
        out_aux[0] = 0.5f * klm + 0.1f * ortho;  // SEQ/PRED = 0.5
    }
}

// -------------------- launch --------------------
extern "C" void kernel_launch(void* const* d_in, const int* in_sizes, int n_in,
                              void* d_out, int out_size) {
    const float* x = (const float*)d_in[0];      // (B, N, D) fp32
    const float* dict = (const float*)d_in[1];   // (C, D) fp32
    float* out = (float*)d_out;
    float* out_common = out;
    float* out_res = out + (size_t)M_ROWS * DDIM;
    float* out_aux = out + (size_t)2 * M_ROWS * DDIM;

    cudaFuncSetAttribute(pass1_kernel, cudaFuncAttributeMaxDynamicSharedMemorySize,
                         SMEM_BYTES);

    // pass3 split in 3 so pass1 is the 4th launch (ncu -s 5 -c 1 lands there)
    pass3_kernel<<<6, 256>>>(dict, 0);
    pass3_kernel<<<5, 256>>>(dict, 6);
    pass3_kernel<<<5, 256>>>(dict, 11);
    pass1_kernel<<<NBLK, 512, SMEM_BYTES>>>(x, dict, out_common, out_res);
    reduce_f_kernel<<<CDIM, 256>>>();
    pass2_kernel<<<P2_GRID, 256>>>();
    pass4_kernel<<<1, 256>>>(out_aux);
}

// round 7
// speedup vs baseline: 1.4995x; 1.4995x over previous
#include <cuda_runtime.h>
#include <cstdint>

// Problem constants
#define M_ROWS (16 * 8192)   // B*N = 131072
#define DDIM 128
#define CDIM 64
#define INV_TEMP (1.0f / 6.0f)   // temp = 2*(1+192/96) = 6

// Pass-1 tiling: 256 threads, 4 rows x 8 cols per thread (best FMA/LDS ratio)
#define BR 128
#define NBLK (M_ROWS / BR)   // 1024
#define XS_STRIDE 132        // x tile row stride (floats)
#define DT_STRIDE 68         // dictT row stride (floats)

#define SMEM_FLOATS (128 * DT_STRIDE + BR * XS_STRIDE + 8 * 64)
#define SMEM_BYTES (SMEM_FLOATS * 4)

#define P2_GRID (M_ROWS / 64)  // 2048

// -------------------- scratch (device globals; no allocs) --------------------
__device__ __align__(16) float g_q[(size_t)M_ROWS * CDIM];
__device__ __align__(16) float g_t[(size_t)M_ROWS * CDIM];
__device__ float g_logS[M_ROWS];
__device__ __align__(16) float g_fpart[CDIM * NBLK];
__device__ float g_f[CDIM];
__device__ float g_klpart[P2_GRID];
__device__ float g_orthopart[16];

// -------------------- packed f32x2 helpers --------------------
__device__ __forceinline__ unsigned long long pack_dup(float x) {
    unsigned long long r;
    unsigned int xu = __float_as_uint(x);
    asm("mov.b64 %0, {%1, %1};" : "=l"(r) : "r"(xu));
    return r;
}
__device__ __forceinline__ void fma2(unsigned long long& acc,
                                     unsigned long long a,
                                     unsigned long long b) {
    asm("fma.rn.f32x2 %0, %1, %2, %0;" : "+l"(acc) : "l"(a), "l"(b));
}
__device__ __forceinline__ void unpack2(unsigned long long v, float& lo, float& hi) {
    unsigned int l, h;
    asm("mov.b64 {%0, %1}, %2;" : "=r"(l), "=r"(h) : "l"(v));
    lo = __uint_as_float(l);
    hi = __uint_as_float(h);
}

// -------------------- kernel 1: GEMM + register softmax/topk + outputs -------
__global__ __launch_bounds__(256, 1) void pass1_kernel(
    const float* __restrict__ x,
    const float* __restrict__ dict,
    float* __restrict__ out_common,
    float* __restrict__ out_res) {
    extern __shared__ float sm[];
    float* dictT = sm;                           // [128][68]: dictT[d][c]
    float* x_s = sm + 128 * DT_STRIDE;           // [128][132]
    float* wsum = x_s + BR * XS_STRIDE;          // [8][64] col-sum partials

    const int tid = threadIdx.x;
    const int row0 = blockIdx.x * BR;

    // --- load dict transposed (conflict-free writes): 2048 float4
    {
        const int c = tid & 63;
        const int base = tid >> 6;  // 0..3
        const float4* dsrc = reinterpret_cast<const float4*>(dict);
#pragma unroll
        for (int j = 0; j < 8; ++j) {
            int dch = base + 4 * j;           // 0..31
            float4 v = dsrc[c * 32 + dch];
            int d0 = dch * 4;
            dictT[(d0 + 0) * DT_STRIDE + c] = v.x;
            dictT[(d0 + 1) * DT_STRIDE + c] = v.y;
            dictT[(d0 + 2) * DT_STRIDE + c] = v.z;
            dictT[(d0 + 3) * DT_STRIDE + c] = v.w;
        }
    }
    // --- load x tile (coalesced float4): 4096
    {
        const float4* xsrc = reinterpret_cast<const float4*>(x + (size_t)row0 * DDIM);
#pragma unroll
        for (int j = 0; j < 16; ++j) {
            int idx4 = tid + 256 * j;
            float4 v = xsrc[idx4];
            int r = idx4 >> 5;
            int d0 = (idx4 & 31) * 4;
            *reinterpret_cast<float4*>(&x_s[r * XS_STRIDE + d0]) = v;
        }
    }
    __syncthreads();

    const int rg = tid >> 3;   // 0..31
    const int cg = tid & 7;    // 0..7
    const int r0 = rg * 4;
    const int lane = tid & 31;
    const int warp = tid >> 5;

    // --- GEMM: 4 rows x 8 cols (f32x2 packed, 16 accumulators)
    float s[4][8];
    {
        unsigned long long acc[4][4];
#pragma unroll
        for (int i = 0; i < 4; ++i)
#pragma unroll
            for (int p = 0; p < 4; ++p) acc[i][p] = 0ull;

        const ulonglong2* dptr =
            reinterpret_cast<const ulonglong2*>(dictT) + cg * 2;  // 17 per d-row
#pragma unroll 8
        for (int k = 0; k < DDIM; ++k) {
            unsigned long long xp0 = pack_dup(x_s[(r0 + 0) * XS_STRIDE + k]);
            unsigned long long xp1 = pack_dup(x_s[(r0 + 1) * XS_STRIDE + k]);
            unsigned long long xp2 = pack_dup(x_s[(r0 + 2) * XS_STRIDE + k]);
            unsigned long long xp3 = pack_dup(x_s[(r0 + 3) * XS_STRIDE + k]);
            ulonglong2 dA = dptr[k * 17];
            ulonglong2 dB = dptr[k * 17 + 1];
            fma2(acc[0][0], xp0, dA.x); fma2(acc[0][1], xp0, dA.y);
            fma2(acc[0][2], xp0, dB.x); fma2(acc[0][3], xp0, dB.y);
            fma2(acc[1][0], xp1, dA.x); fma2(acc[1][1], xp1, dA.y);
            fma2(acc[1][2], xp1, dB.x); fma2(acc[1][3], xp1, dB.y);
            fma2(acc[2][0], xp2, dA.x); fma2(acc[2][1], xp2, dA.y);
            fma2(acc[2][2], xp2, dB.x); fma2(acc[2][3], xp2, dB.y);
            fma2(acc[3][0], xp3, dA.x); fma2(acc[3][1], xp3, dA.y);
            fma2(acc[3][2], xp3, dB.x); fma2(acc[3][3], xp3, dB.y);
        }
#pragma unroll
        for (int i = 0; i < 4; ++i)
#pragma unroll
            for (int p = 0; p < 4; ++p)
                unpack2(acc[i][p], s[i][2 * p], s[i][2 * p + 1]);
    }
    // s[r][j] = score(row r0+r, col 8*cg+j); each row's 64 cols live in the
    // 8 lanes sharing this rg group -> all row ops via shfl.xor 1,2,4.

    // --- row max
    float m[4];
#pragma unroll
    for (int r = 0; r < 4; ++r) {
        float mm = s[r][0];
#pragma unroll
        for (int j = 1; j < 8; ++j) mm = fmaxf(mm, s[r][j]);
        m[r] = mm;
    }
#pragma unroll
    for (int msk = 1; msk <= 4; msk <<= 1)
#pragma unroll
        for (int r = 0; r < 4; ++r)
            m[r] = fmaxf(m[r], __shfl_xor_sync(0xFFFFFFFFu, m[r], msk));

    // --- branchless local top-4 of 8 (strict > keeps lowest index on ties)
    float tv[4][4]; int ti[4][4];
#pragma unroll
    for (int r = 0; r < 4; ++r) {
        unsigned excl = 0;
#pragma unroll
        for (int p = 0; p < 4; ++p) {
            float bm = -1e30f; int bi = 0;
#pragma unroll
            for (int j = 0; j < 8; ++j) {
                bool ok = (((excl >> j) & 1u) == 0u) && (s[r][j] > bm);
                bm = ok ? s[r][j] : bm;
                bi = ok ? j : bi;
            }
            tv[r][p] = bm; ti[r][p] = 8 * cg + bi;
            excl |= 1u << bi;
        }
    }
    // 3-stage merge of sorted top-4 lists (lower col range wins ties)
#pragma unroll
    for (int msk = 1; msk <= 4; msk <<= 1) {
        bool iamA = ((cg & msk) == 0);
#pragma unroll
        for (int r = 0; r < 4; ++r) {
            float pv[4]; int pi[4];
#pragma unroll
            for (int k2 = 0; k2 < 4; ++k2) {
                pv[k2] = __shfl_xor_sync(0xFFFFFFFFu, tv[r][k2], msk);
                pi[k2] = __shfl_xor_sync(0xFFFFFFFFu, ti[r][k2], msk);
            }
            float Av[4], Bv[4]; int Ai[4], Bi[4];
#pragma unroll
            for (int k2 = 0; k2 < 4; ++k2) {
                Av[k2] = iamA ? tv[r][k2] : pv[k2];
                Ai[k2] = iamA ? ti[r][k2] : pi[k2];
                Bv[k2] = iamA ? pv[k2] : tv[r][k2];
                Bi[k2] = iamA ? pi[k2] : ti[r][k2];
            }
            int a = 0, b = 0;
#pragma unroll
            for (int k2 = 0; k2 < 4; ++k2) {
                bool ta = (Av[a] >= Bv[b]);
                tv[r][k2] = ta ? Av[a] : Bv[b];
                ti[r][k2] = ta ? Ai[a] : Bi[b];
                a += ta ? 1 : 0;
                b += ta ? 0 : 1;
            }
        }
    }

    // --- t -> gmem, e = exp(t), row sums S
    float S[4];
#pragma unroll
    for (int r = 0; r < 4; ++r) {
        const int rowg = row0 + r0 + r;
        float t[8];
#pragma unroll
        for (int j = 0; j < 8; ++j) t[j] = (s[r][j] - m[r]) * INV_TEMP;
        float4 t0 = {t[0], t[1], t[2], t[3]};
        float4 t1 = {t[4], t[5], t[6], t[7]};
        float4* tg = reinterpret_cast<float4*>(&g_t[(size_t)rowg * CDIM + 8 * cg]);
        tg[0] = t0; tg[1] = t1;
        float ss = 0.0f;
#pragma unroll
        for (int j = 0; j < 8; ++j) {
            float e = __expf(t[j]);
            s[r][j] = e;
            ss += e;
        }
        S[r] = ss;
    }
#pragma unroll
    for (int msk = 1; msk <= 4; msk <<= 1)
#pragma unroll
        for (int r = 0; r < 4; ++r)
            S[r] += __shfl_xor_sync(0xFFFFFFFFu, S[r], msk);

    if (cg == 0) {
#pragma unroll
        for (int r = 0; r < 4; ++r)
            g_logS[row0 + r0 + r] = __logf(S[r]);
    }

    // --- q -> gmem + per-thread column partials
    float colsum[8];
#pragma unroll
    for (int j = 0; j < 8; ++j) colsum[j] = 0.0f;
#pragma unroll
    for (int r = 0; r < 4; ++r) {
        const int rowg = row0 + r0 + r;
        float invS = 1.0f / S[r];
        float q[8];
#pragma unroll
        for (int j = 0; j < 8; ++j) {
            q[j] = s[r][j] * invS;
            colsum[j] += q[j];
        }
        float4 q0 = {q[0], q[1], q[2], q[3]};
        float4 q1 = {q[4], q[5], q[6], q[7]};
        float4* qg = reinterpret_cast<float4*>(&g_q[(size_t)rowg * CDIM + 8 * cg]);
        qg[0] = q0; qg[1] = q1;
    }
    // reduce colsum across the 4 rg groups of this warp (lanes 0-7 end up owning)
#pragma unroll
    for (int msk = 8; msk <= 16; msk <<= 1)
#pragma unroll
        for (int j = 0; j < 8; ++j)
            colsum[j] += __shfl_xor_sync(0xFFFFFFFFu, colsum[j], msk);
    if (lane < 8) {
#pragma unroll
        for (int j = 0; j < 8; ++j) wsum[warp * 64 + 8 * cg + j] = colsum[j];
    }

    // --- epilogue: gather + outputs, d interleaved by 8 (bank-conflict-free)
#pragma unroll
    for (int r = 0; r < 4; ++r) {
        const int rowg = row0 + r0 + r;
        float e1 = __expf((tv[r][1] - tv[r][0]) * INV_TEMP);
        float e2 = __expf((tv[r][2] - tv[r][0]) * INV_TEMP);
        float e3 = __expf((tv[r][3] - tv[r][0]) * INV_TEMP);
        float wn = 1.0f / (1.0f + e1 + e2 + e3);
        float w0 = wn, w1 = e1 * wn, w2 = e2 * wn, w3 = e3 * wn;
        const int i0 = ti[r][0], i1 = ti[r][1], i2 = ti[r][2], i3 = ti[r][3];
        const float* xr = &x_s[(r0 + r) * XS_STRIDE];
        float* oc = out_common + (size_t)rowg * DDIM;
        float* orr = out_res + (size_t)rowg * DDIM;
#pragma unroll
        for (int t16 = 0; t16 < 16; ++t16) {
            int d = 8 * t16 + cg;
            const float* drow = &dictT[d * DT_STRIDE];
            float cm = w0 * drow[i0] + w1 * drow[i1] + w2 * drow[i2] + w3 * drow[i3];
            float xv = xr[d];
            oc[d] = cm;
            orr[d] = xv - cm;
        }
    }
    __syncthreads();

    // --- final column sums (8 warps x 64 cols) -> partials
    if (tid < CDIM) {
        float sum = 0.0f;
#pragma unroll
        for (int w = 0; w < 8; ++w) sum += wsum[w * 64 + tid];
        g_fpart[tid * NBLK + blockIdx.x] = sum;
    }
}

// -------------------- kernel 1b: reduce column-sum partials --------------------
__global__ __launch_bounds__(256) void reduce_f_kernel() {
    __shared__ float ws[8];
    const int c = blockIdx.x;
    const int tid = threadIdx.x;
    const float* src = &g_fpart[c * NBLK];
    float sum = 0.0f;
#pragma unroll
    for (int j = 0; j < NBLK / 256; ++j) sum += src[tid + 256 * j];
#pragma unroll
    for (int o = 16; o; o >>= 1) sum += __shfl_xor_sync(0xFFFFFFFFu, sum, o);
    if ((tid & 31) == 0) ws[tid >> 5] = sum;
    __syncthreads();
    if (tid == 0) {
        float t = 0.0f;
#pragma unroll
        for (int i = 0; i < 8; ++i) t += ws[i];
        g_f[c] = t;
    }
}

// -------------------- kernel 2: KL (no per-element transcendentals) ----------
__global__ __launch_bounds__(256) void pass2_kernel() {
    __shared__ float invf_s[CDIM], lw_s[CDIM];
    __shared__ float wsum[8];
    const int tid = threadIdx.x;
    if (tid < CDIM) {
        float f = g_f[tid];
        invf_s[tid] = 1.0f / f;
        lw_s[tid] = __logf(f) / f;
    }
    __syncthreads();

    const int r = blockIdx.x * 64 + (tid >> 2);
    const int qd = tid & 3;
    const int c0 = qd * 16;
    const float4* qp = reinterpret_cast<const float4*>(g_q + (size_t)r * CDIM + c0);
    const float4* tp = reinterpret_cast<const float4*>(g_t + (size_t)r * CDIM + c0);

    float W = 0.0f, V = 0.0f, L = 0.0f;
#pragma unroll
    for (int j4 = 0; j4 < 4; ++j4) {
        float4 qv = qp[j4];
        float4 tvv = tp[j4];
        float qa[4] = {qv.x, qv.y, qv.z, qv.w};
        float ta[4] = {tvv.x, tvv.y, tvv.z, tvv.w};
#pragma unroll
        for (int i = 0; i < 4; ++i) {
            int c = c0 + j4 * 4 + i;
            float u = qa[i] * qa[i];
            float a = u * invf_s[c];
            W += a;
            V = fmaf(a, ta[i], V);
            L = fmaf(u, lw_s[c], L);
        }
    }
    W += __shfl_xor_sync(0xFFFFFFFFu, W, 1);
    W += __shfl_xor_sync(0xFFFFFFFFu, W, 2);
    V += __shfl_xor_sync(0xFFFFFFFFu, V, 1);
    V += __shfl_xor_sync(0xFFFFFFFFu, V, 2);
    L += __shfl_xor_sync(0xFFFFFFFFu, L, 1);
    L += __shfl_xor_sync(0xFFFFFFFFu, L, 2);

    float tm = 0.0f;
    if (qd == 0) tm = (V - L) / W - __logf(W) - g_logS[r];
    tm += __shfl_xor_sync(0xFFFFFFFFu, tm, 4);
    tm += __shfl_xor_sync(0xFFFFFFFFu, tm, 8);
    tm += __shfl_xor_sync(0xFFFFFFFFu, tm, 16);
    if ((tid & 31) == 0) wsum[tid >> 5] = tm;
    __syncthreads();
    if (tid == 0) {
        float t = 0.0f;
#pragma unroll
        for (int i = 0; i < 8; ++i) t += wsum[i];
        g_klpart[blockIdx.x] = t;
    }
}

// -------------------- kernel 3: ortho gram (split across 3 launches) ---------
#define OT_STRIDE 65
__global__ __launch_bounds__(256) void pass3_kernel(const float* __restrict__ dict,
                                                    int base) {
    __shared__ float dT[DDIM * OT_STRIDE];
    __shared__ float ws[8];
    const int tid = threadIdx.x;
    {
        const float4* dsrc = reinterpret_cast<const float4*>(dict);
#pragma unroll
        for (int it = 0; it < 8; ++it) {
            int idx = tid + 256 * it;
            int c = idx >> 5;
            int dch = idx & 31;
            float4 v = dsrc[c * 32 + dch];
            int d0 = dch * 4;
            dT[(d0 + 0) * OT_STRIDE + c] = v.x;
            dT[(d0 + 1) * OT_STRIDE + c] = v.y;
            dT[(d0 + 2) * OT_STRIDE + c] = v.z;
            dT[(d0 + 3) * OT_STRIDE + c] = v.w;
        }
    }
    __syncthreads();

    const int p = (base + blockIdx.x) * 256 + tid;
    const int i = p >> 6, j = p & 63;
    float dot = 0.0f;
#pragma unroll 8
    for (int d = 0; d < DDIM; ++d)
        dot = fmaf(dT[d * OT_STRIDE + i], dT[d * OT_STRIDE + j], dot);
    float diff = dot - ((i == j) ? 1.0f : 0.0f);
    float acc = diff * diff;

#pragma unroll
    for (int o = 16; o; o >>= 1) acc += __shfl_xor_sync(0xFFFFFFFFu, acc, o);
    if ((tid & 31) == 0) ws[tid >> 5] = acc;
    __syncthreads();
    if (tid == 0) {
        float t = 0.0f;
#pragma unroll
        for (int k = 0; k < 8; ++k) t += ws[k];
        g_orthopart[base + blockIdx.x] = t;
    }
}

// -------------------- kernel 4: finalize aux --------------------
__global__ __launch_bounds__(256) void pass4_kernel(float* __restrict__ out_aux) {
    __shared__ float ws[8];
    const int tid = threadIdx.x;
    float kl = 0.0f;
#pragma unroll
    for (int j = 0; j < P2_GRID / 256; ++j) kl += g_klpart[tid + 256 * j];
#pragma unroll
    for (int o = 16; o; o >>= 1) kl += __shfl_xor_sync(0xFFFFFFFFu, kl, o);
    if ((tid & 31) == 0) ws[tid >> 5] = kl;
    __syncthreads();
    if (tid == 0) {
        float t = 0.0f;
#pragma unroll
        for (int i = 0; i < 8; ++i) t += ws[i];
        float ortho = 0.0f;
#pragma unroll
        for (int i = 0; i < 16; ++i) ortho += g_orthopart[i];
        ortho /= (float)(CDIM * CDIM);
        float klm = t / (float)M_ROWS;
        out_aux[0] = 0.5f * klm + 0.1f * ortho;  // SEQ/PRED = 0.5
    }
}

// -------------------- launch --------------------
extern "C" void kernel_launch(void* const* d_in, const int* in_sizes, int n_in,
                              void* d_out, int out_size) {
    const float* x = (const float*)d_in[0];
    const float* dict = (const float*)d_in[1];
    float* out = (float*)d_out;
    float* out_common = out;
    float* out_res = out + (size_t)M_ROWS * DDIM;
    float* out_aux = out + (size_t)2 * M_ROWS * DDIM;

    cudaFuncSetAttribute(pass1_kernel, cudaFuncAttributeMaxDynamicSharedMemorySize,
                         SMEM_BYTES);

    // pass3 split in 3 so pass1 is the 4th launch (ncu -s 5 -c 1 lands there)
    pass3_kernel<<<6, 256>>>(dict, 0);
    pass3_kernel<<<5, 256>>>(dict, 6);
    pass3_kernel<<<5, 256>>>(dict, 11);
    pass1_kernel<<<NBLK, 256, SMEM_BYTES>>>(x, dict, out_common, out_res);
    reduce_f_kernel<<<CDIM, 256>>>();
    pass2_kernel<<<P2_GRID, 256>>>();
    pass4_kernel<<<1, 256>>>(out_aux);
}

// round 8
// speedup vs baseline: 1.5714x; 1.0480x over previous
#include <cuda_runtime.h>
#include <cstdint>

// Problem constants
#define M_ROWS (16 * 8192)   // B*N = 131072
#define DDIM 128
#define CDIM 64
#define INV_TEMP (1.0f / 6.0f)   // temp = 2*(1+192/96) = 6

// Pass-1 tiling: 256 threads, thread rows = rg + 32*i (conflict-free x loads)
#define BR 128
#define NBLK (M_ROWS / BR)   // 1024
#define XS_STRIDE 132        // x tile row stride (floats); 132 % 32 = 4 banks
#define DT_STRIDE 68         // dictT [d][c] row stride
#define DS_STRIDE 132        // dict_s [c][d] row stride

#define SMEM_FLOATS (128 * DT_STRIDE + BR * XS_STRIDE + CDIM * DS_STRIDE + 8 * 64)
#define SMEM_BYTES (SMEM_FLOATS * 4)   // 138240

#define P2_GRID (M_ROWS / 64)  // 2048

// -------------------- scratch (device globals; no allocs) --------------------
__device__ __align__(16) float g_q[(size_t)M_ROWS * CDIM];
__device__ __align__(16) float g_t[(size_t)M_ROWS * CDIM];
__device__ float g_logS[M_ROWS];
__device__ __align__(16) float g_fpart[CDIM * NBLK];
__device__ float g_f[CDIM];
__device__ float g_klpart[P2_GRID];
__device__ float g_orthopart[16];

// -------------------- packed f32x2 helpers --------------------
__device__ __forceinline__ unsigned long long pack_dup(float x) {
    unsigned long long r;
    unsigned int xu = __float_as_uint(x);
    asm("mov.b64 %0, {%1, %1};" : "=l"(r) : "r"(xu));
    return r;
}
__device__ __forceinline__ void fma2(unsigned long long& acc,
                                     unsigned long long a,
                                     unsigned long long b) {
    asm("fma.rn.f32x2 %0, %1, %2, %0;" : "+l"(acc) : "l"(a), "l"(b));
}
__device__ __forceinline__ void unpack2(unsigned long long v, float& lo, float& hi) {
    unsigned int l, h;
    asm("mov.b64 {%0, %1}, %2;" : "=r"(l), "=r"(h) : "l"(v));
    lo = __uint_as_float(l);
    hi = __uint_as_float(h);
}

// -------------------- kernel 1: GEMM + register softmax/topk + outputs -------
__global__ __launch_bounds__(256, 1) void pass1_kernel(
    const float* __restrict__ x,
    const float* __restrict__ dict,
    float* __restrict__ out_common,
    float* __restrict__ out_res) {
    extern __shared__ float sm[];
    float* dictT = sm;                               // [128][68]  (d-major)
    float* x_s = dictT + 128 * DT_STRIDE;            // [128][132]
    float* dict_s = x_s + BR * XS_STRIDE;            // [64][132]  (c-major)
    float* wsum = dict_s + CDIM * DS_STRIDE;         // [8][64]

    const int tid = threadIdx.x;
    const int row0 = blockIdx.x * BR;

    // --- stage dict: both layouts (2048 float4 reads)
    {
        const float4* dsrc = reinterpret_cast<const float4*>(dict);
#pragma unroll
        for (int it = 0; it < 8; ++it) {
            int idx = tid + 256 * it;          // 0..2047
            int c = idx >> 5;                  // 0..63
            int dch = idx & 31;                // 0..31
            float4 v = dsrc[idx];
            int d0 = dch * 4;
            dictT[(d0 + 0) * DT_STRIDE + c] = v.x;
            dictT[(d0 + 1) * DT_STRIDE + c] = v.y;
            dictT[(d0 + 2) * DT_STRIDE + c] = v.z;
            dictT[(d0 + 3) * DT_STRIDE + c] = v.w;
            *reinterpret_cast<float4*>(&dict_s[c * DS_STRIDE + d0]) = v;
        }
    }
    // --- stage x tile (coalesced float4): 4096
    {
        const float4* xsrc = reinterpret_cast<const float4*>(x + (size_t)row0 * DDIM);
#pragma unroll
        for (int j = 0; j < 16; ++j) {
            int idx4 = tid + 256 * j;
            float4 v = xsrc[idx4];
            int r = idx4 >> 5;
            int d0 = (idx4 & 31) * 4;
            *reinterpret_cast<float4*>(&x_s[r * XS_STRIDE + d0]) = v;
        }
    }
    __syncthreads();

    const int rg = tid >> 3;   // 0..31 -> thread rows rg + 32*i
    const int cg = tid & 7;    // 0..7  -> cols 8*cg..8*cg+7 (scores)
    const int lane = tid & 31;
    const int warp = tid >> 5;

    // --- GEMM: 4 rows x 8 cols, x loaded as float4 per 4 k's
    float s[4][8];
    {
        unsigned long long acc[4][4];
#pragma unroll
        for (int i = 0; i < 4; ++i)
#pragma unroll
            for (int p = 0; p < 4; ++p) acc[i][p] = 0ull;

        const ulonglong2* dptr =
            reinterpret_cast<const ulonglong2*>(dictT) + cg * 2;  // 17 per d-row
#pragma unroll 4
        for (int k4 = 0; k4 < DDIM / 4; ++k4) {
            float4 xq[4];
#pragma unroll
            for (int i = 0; i < 4; ++i)
                xq[i] = *reinterpret_cast<const float4*>(
                    &x_s[(rg + 32 * i) * XS_STRIDE + k4 * 4]);
#pragma unroll
            for (int kk = 0; kk < 4; ++kk) {
                const int k = k4 * 4 + kk;
                ulonglong2 dA = dptr[k * 17];
                ulonglong2 dB = dptr[k * 17 + 1];
                unsigned long long xp0 = pack_dup((&xq[0].x)[kk]);
                unsigned long long xp1 = pack_dup((&xq[1].x)[kk]);
                unsigned long long xp2 = pack_dup((&xq[2].x)[kk]);
                unsigned long long xp3 = pack_dup((&xq[3].x)[kk]);
                fma2(acc[0][0], xp0, dA.x); fma2(acc[0][1], xp0, dA.y);
                fma2(acc[0][2], xp0, dB.x); fma2(acc[0][3], xp0, dB.y);
                fma2(acc[1][0], xp1, dA.x); fma2(acc[1][1], xp1, dA.y);
                fma2(acc[1][2], xp1, dB.x); fma2(acc[1][3], xp1, dB.y);
                fma2(acc[2][0], xp2, dA.x); fma2(acc[2][1], xp2, dA.y);
                fma2(acc[2][2], xp2, dB.x); fma2(acc[2][3], xp2, dB.y);
                fma2(acc[3][0], xp3, dA.x); fma2(acc[3][1], xp3, dA.y);
                fma2(acc[3][2], xp3, dB.x); fma2(acc[3][3], xp3, dB.y);
            }
        }
#pragma unroll
        for (int i = 0; i < 4; ++i)
#pragma unroll
            for (int p = 0; p < 4; ++p)
                unpack2(acc[i][p], s[i][2 * p], s[i][2 * p + 1]);
    }
    // s[i][j] = score(row rg+32i, col 8*cg+j); row ops via shfl.xor 1,2,4.

    // --- row max
    float m[4];
#pragma unroll
    for (int r = 0; r < 4; ++r) {
        float mm = s[r][0];
#pragma unroll
        for (int j = 1; j < 8; ++j) mm = fmaxf(mm, s[r][j]);
        m[r] = mm;
    }
#pragma unroll
    for (int msk = 1; msk <= 4; msk <<= 1)
#pragma unroll
        for (int r = 0; r < 4; ++r)
            m[r] = fmaxf(m[r], __shfl_xor_sync(0xFFFFFFFFu, m[r], msk));

    // --- branchless local top-4 of 8 (strict > keeps lowest index on ties)
    float tv[4][4]; int ti[4][4];
#pragma unroll
    for (int r = 0; r < 4; ++r) {
        unsigned excl = 0;
#pragma unroll
        for (int p = 0; p < 4; ++p) {
            float bm = -1e30f; int bi = 0;
#pragma unroll
            for (int j = 0; j < 8; ++j) {
                bool ok = (((excl >> j) & 1u) == 0u) && (s[r][j] > bm);
                bm = ok ? s[r][j] : bm;
                bi = ok ? j : bi;
            }
            tv[r][p] = bm; ti[r][p] = 8 * cg + bi;
            excl |= 1u << bi;
        }
    }
    // 3-stage merge of sorted top-4 lists (lower col range wins ties)
#pragma unroll
    for (int msk = 1; msk <= 4; msk <<= 1) {
        bool iamA = ((cg & msk) == 0);
#pragma unroll
        for (int r = 0; r < 4; ++r) {
            float pv[4]; int pi[4];
#pragma unroll
            for (int k2 = 0; k2 < 4; ++k2) {
                pv[k2] = __shfl_xor_sync(0xFFFFFFFFu, tv[r][k2], msk);
                pi[k2] = __shfl_xor_sync(0xFFFFFFFFu, ti[r][k2], msk);
            }
            float Av[4], Bv[4]; int Ai[4], Bi[4];
#pragma unroll
            for (int k2 = 0; k2 < 4; ++k2) {
                Av[k2] = iamA ? tv[r][k2] : pv[k2];
                Ai[k2] = iamA ? ti[r][k2] : pi[k2];
                Bv[k2] = iamA ? pv[k2] : tv[r][k2];
                Bi[k2] = iamA ? pi[k2] : ti[r][k2];
            }
            int a = 0, b = 0;
#pragma unroll
            for (int k2 = 0; k2 < 4; ++k2) {
                bool ta = (Av[a] >= Bv[b]);
                tv[r][k2] = ta ? Av[a] : Bv[b];
                ti[r][k2] = ta ? Ai[a] : Bi[b];
                a += ta ? 1 : 0;
                b += ta ? 0 : 1;
            }
        }
    }

    // --- t -> gmem, e = exp(t), row sums S
    float S[4];
#pragma unroll
    for (int r = 0; r < 4; ++r) {
        const int rowg = row0 + rg + 32 * r;
        float t[8];
#pragma unroll
        for (int j = 0; j < 8; ++j) t[j] = (s[r][j] - m[r]) * INV_TEMP;
        float4 t0 = {t[0], t[1], t[2], t[3]};
        float4 t1 = {t[4], t[5], t[6], t[7]};
        float4* tg = reinterpret_cast<float4*>(&g_t[(size_t)rowg * CDIM + 8 * cg]);
        tg[0] = t0; tg[1] = t1;
        float ss = 0.0f;
#pragma unroll
        for (int j = 0; j < 8; ++j) {
            float e = __expf(t[j]);
            s[r][j] = e;
            ss += e;
        }
        S[r] = ss;
    }
#pragma unroll
    for (int msk = 1; msk <= 4; msk <<= 1)
#pragma unroll
        for (int r = 0; r < 4; ++r)
            S[r] += __shfl_xor_sync(0xFFFFFFFFu, S[r], msk);

    if (cg == 0) {
#pragma unroll
        for (int r = 0; r < 4; ++r)
            g_logS[row0 + rg + 32 * r] = __logf(S[r]);
    }

    // --- q -> gmem + per-thread column partials
    float colsum[8];
#pragma unroll
    for (int j = 0; j < 8; ++j) colsum[j] = 0.0f;
#pragma unroll
    for (int r = 0; r < 4; ++r) {
        const int rowg = row0 + rg + 32 * r;
        float invS = 1.0f / S[r];
        float q[8];
#pragma unroll
        for (int j = 0; j < 8; ++j) {
            q[j] = s[r][j] * invS;
            colsum[j] += q[j];
        }
        float4 q0 = {q[0], q[1], q[2], q[3]};
        float4 q1 = {q[4], q[5], q[6], q[7]};
        float4* qg = reinterpret_cast<float4*>(&g_q[(size_t)rowg * CDIM + 8 * cg]);
        qg[0] = q0; qg[1] = q1;
    }
#pragma unroll
    for (int msk = 8; msk <= 16; msk <<= 1)
#pragma unroll
        for (int j = 0; j < 8; ++j)
            colsum[j] += __shfl_xor_sync(0xFFFFFFFFu, colsum[j], msk);
    if (lane < 8) {
#pragma unroll
        for (int j = 0; j < 8; ++j) wsum[warp * 64 + 8 * cg + j] = colsum[j];
    }

    // --- epilogue: float4 gather from dict_s + coalesced float4 outputs
#pragma unroll
    for (int r = 0; r < 4; ++r) {
        const int rowg = row0 + rg + 32 * r;
        float e1 = __expf((tv[r][1] - tv[r][0]) * INV_TEMP);
        float e2 = __expf((tv[r][2] - tv[r][0]) * INV_TEMP);
        float e3 = __expf((tv[r][3] - tv[r][0]) * INV_TEMP);
        float wn = 1.0f / (1.0f + e1 + e2 + e3);
        float w0 = wn, w1 = e1 * wn, w2 = e2 * wn, w3 = e3 * wn;
        const float* d0p = &dict_s[ti[r][0] * DS_STRIDE];
        const float* d1p = &dict_s[ti[r][1] * DS_STRIDE];
        const float* d2p = &dict_s[ti[r][2] * DS_STRIDE];
        const float* d3p = &dict_s[ti[r][3] * DS_STRIDE];
        const float* xr = &x_s[(rg + 32 * r) * XS_STRIDE];
        float* oc = out_common + (size_t)rowg * DDIM;
        float* orr = out_res + (size_t)rowg * DDIM;
#pragma unroll
        for (int dd4 = 0; dd4 < 4; ++dd4) {
            const int d = dd4 * 32 + cg * 4;   // 128B-contiguous across 8 cg lanes
            float4 a0 = *reinterpret_cast<const float4*>(d0p + d);
            float4 a1 = *reinterpret_cast<const float4*>(d1p + d);
            float4 a2 = *reinterpret_cast<const float4*>(d2p + d);
            float4 a3 = *reinterpret_cast<const float4*>(d3p + d);
            float4 xv = *reinterpret_cast<const float4*>(xr + d);
            float4 cm;
            cm.x = w0 * a0.x + w1 * a1.x + w2 * a2.x + w3 * a3.x;
            cm.y = w0 * a0.y + w1 * a1.y + w2 * a2.y + w3 * a3.y;
            cm.z = w0 * a0.z + w1 * a1.z + w2 * a2.z + w3 * a3.z;
            cm.w = w0 * a0.w + w1 * a1.w + w2 * a2.w + w3 * a3.w;
            *reinterpret_cast<float4*>(oc + d) = cm;
            float4 rs;
            rs.x = xv.x - cm.x; rs.y = xv.y - cm.y;
            rs.z = xv.z - cm.z; rs.w = xv.w - cm.w;
            *reinterpret_cast<float4*>(orr + d) = rs;
        }
    }
    __syncthreads();

    // --- final column sums (8 warps x 64 cols) -> partials
    if (tid < CDIM) {
        float sum = 0.0f;
#pragma unroll
        for (int w = 0; w < 8; ++w) sum += wsum[w * 64 + tid];
        g_fpart[tid * NBLK + blockIdx.x] = sum;
    }
}

// -------------------- kernel 1b: reduce column-sum partials --------------------
__global__ __launch_bounds__(256) void reduce_f_kernel() {
    __shared__ float ws[8];
    const int c = blockIdx.x;
    const int tid = threadIdx.x;
    const float* src = &g_fpart[c * NBLK];
    float sum = 0.0f;
#pragma unroll
    for (int j = 0; j < NBLK / 256; ++j) sum += src[tid + 256 * j];
#pragma unroll
    for (int o = 16; o; o >>= 1) sum += __shfl_xor_sync(0xFFFFFFFFu, sum, o);
    if ((tid & 31) == 0) ws[tid >> 5] = sum;
    __syncthreads();
    if (tid == 0) {
        float t = 0.0f;
#pragma unroll
        for (int i = 0; i < 8; ++i) t += ws[i];
        g_f[c] = t;
    }
}

// -------------------- kernel 2: KL (no per-element transcendentals) ----------
__global__ __launch_bounds__(256) void pass2_kernel() {
    __shared__ float invf_s[CDIM], lw_s[CDIM];
    __shared__ float wsum[8];
    const int tid = threadIdx.x;
    if (tid < CDIM) {
        float f = g_f[tid];
        invf_s[tid] = 1.0f / f;
        lw_s[tid] = __logf(f) / f;
    }
    __syncthreads();

    const int r = blockIdx.x * 64 + (tid >> 2);
    const int qd = tid & 3;
    const int c0 = qd * 16;
    const float4* qp = reinterpret_cast<const float4*>(g_q + (size_t)r * CDIM + c0);
    const float4* tp = reinterpret_cast<const float4*>(g_t + (size_t)r * CDIM + c0);

    float W = 0.0f, V = 0.0f, L = 0.0f;
#pragma unroll
    for (int j4 = 0; j4 < 4; ++j4) {
        float4 qv = qp[j4];
        float4 tvv = tp[j4];
        float qa[4] = {qv.x, qv.y, qv.z, qv.w};
        float ta[4] = {tvv.x, tvv.y, tvv.z, tvv.w};
#pragma unroll
        for (int i = 0; i < 4; ++i) {
            int c = c0 + j4 * 4 + i;
            float u = qa[i] * qa[i];
            float a = u * invf_s[c];
            W += a;
            V = fmaf(a, ta[i], V);
            L = fmaf(u, lw_s[c], L);
        }
    }
    W += __shfl_xor_sync(0xFFFFFFFFu, W, 1);
    W += __shfl_xor_sync(0xFFFFFFFFu, W, 2);
    V += __shfl_xor_sync(0xFFFFFFFFu, V, 1);
    V += __shfl_xor_sync(0xFFFFFFFFu, V, 2);
    L += __shfl_xor_sync(0xFFFFFFFFu, L, 1);
    L += __shfl_xor_sync(0xFFFFFFFFu, L, 2);

    float tm = 0.0f;
    if (qd == 0) tm = (V - L) / W - __logf(W) - g_logS[r];
    tm += __shfl_xor_sync(0xFFFFFFFFu, tm, 4);
    tm += __shfl_xor_sync(0xFFFFFFFFu, tm, 8);
    tm += __shfl_xor_sync(0xFFFFFFFFu, tm, 16);
    if ((tid & 31) == 0) wsum[tid >> 5] = tm;
    __syncthreads();
    if (tid == 0) {
        float t = 0.0f;
#pragma unroll
        for (int i = 0; i < 8; ++i) t += wsum[i];
        g_klpart[blockIdx.x] = t;
    }
}

// -------------------- kernel 3: ortho gram (split across 3 launches) ---------
#define OT_STRIDE 65
__global__ __launch_bounds__(256) void pass3_kernel(const float* __restrict__ dict,
                                                    int base) {
    __shared__ float dT[DDIM * OT_STRIDE];
    __shared__ float ws[8];
    const int tid = threadIdx.x;
    {
        const float4* dsrc = reinterpret_cast<const float4*>(dict);
#pragma unroll
        for (int it = 0; it < 8; ++it) {
            int idx = tid + 256 * it;
            int c = idx >> 5;
            int dch = idx & 31;
            float4 v = dsrc[c * 32 + dch];
            int d0 = dch * 4;
            dT[(d0 + 0) * OT_STRIDE + c] = v.x;
            dT[(d0 + 1) * OT_STRIDE + c] = v.y;
            dT[(d0 + 2) * OT_STRIDE + c] = v.z;
            dT[(d0 + 3) * OT_STRIDE + c] = v.w;
        }
    }
    __syncthreads();

    const int p = (base + blockIdx.x) * 256 + tid;
    const int i = p >> 6, j = p & 63;
    float dot = 0.0f;
#pragma unroll 8
    for (int d = 0; d < DDIM; ++d)
        dot = fmaf(dT[d * OT_STRIDE + i], dT[d * OT_STRIDE + j], dot);
    float diff = dot - ((i == j) ? 1.0f : 0.0f);
    float acc = diff * diff;

#pragma unroll
    for (int o = 16; o; o >>= 1) acc += __shfl_xor_sync(0xFFFFFFFFu, acc, o);
    if ((tid & 31) == 0) ws[tid >> 5] = acc;
    __syncthreads();
    if (tid == 0) {
        float t = 0.0f;
#pragma unroll
        for (int k = 0; k < 8; ++k) t += ws[k];
        g_orthopart[base + blockIdx.x] = t;
    }
}

// -------------------- kernel 4: finalize aux --------------------
__global__ __launch_bounds__(256) void pass4_kernel(float* __restrict__ out_aux) {
    __shared__ float ws[8];
    const int tid = threadIdx.x;
    float kl = 0.0f;
#pragma unroll
    for (int j = 0; j < P2_GRID / 256; ++j) kl += g_klpart[tid + 256 * j];
#pragma unroll
    for (int o = 16; o; o >>= 1) kl += __shfl_xor_sync(0xFFFFFFFFu, kl, o);
    if ((tid & 31) == 0) ws[tid >> 5] = kl;
    __syncthreads();
    if (tid == 0) {
        float t = 0.0f;
#pragma unroll
        for (int i = 0; i < 8; ++i) t += ws[i];
        float ortho = 0.0f;
#pragma unroll
        for (int i = 0; i < 16; ++i) ortho += g_orthopart[i];
        ortho /= (float)(CDIM * CDIM);
        float klm = t / (float)M_ROWS;
        out_aux[0] = 0.5f * klm + 0.1f * ortho;  // SEQ/PRED = 0.5
    }
}

// -------------------- launch --------------------
extern "C" void kernel_launch(void* const* d_in, const int* in_sizes, int n_in,
                              void* d_out, int out_size) {
    const float* x = (const float*)d_in[0];
    const float* dict = (const float*)d_in[1];
    float* out = (float*)d_out;
    float* out_common = out;
    float* out_res = out + (size_t)M_ROWS * DDIM;
    float* out_aux = out + (size_t)2 * M_ROWS * DDIM;

    cudaFuncSetAttribute(pass1_kernel, cudaFuncAttributeMaxDynamicSharedMemorySize,
                         SMEM_BYTES);

    // pass3 split in 3 so pass1 is the 4th launch (ncu -s 5 -c 1 lands there)
    pass3_kernel<<<6, 256>>>(dict, 0);
    pass3_kernel<<<5, 256>>>(dict, 6);
    pass3_kernel<<<5, 256>>>(dict, 11);
    pass1_kernel<<<NBLK, 256, SMEM_BYTES>>>(x, dict, out_common, out_res);
    reduce_f_kernel<<<CDIM, 256>>>();
    pass2_kernel<<<P2_GRID, 256>>>();
    pass4_kernel<<<1, 256>>>(out_aux);
}